// round 5
// baseline (speedup 1.0000x reference)
#include <cuda_runtime.h>

#define HWD (96*96*96)        // 884736
#define NB  4
#define NVOX (NB*HWD)         // 3538944
#define Q4  (HWD/4)           // 221184 float4 groups per (b, channel)
#define BLOCK 256
#define GRID  (NVOX / 4 / BLOCK)   // 3456, exact

__device__ double       g_sum    = 0.0;
__device__ int          g_cnt    = 0;
__device__ unsigned int g_retire = 0u;

// Warp-uniform scale/shift: read via LDCU into uniform registers (no per-thread regs).
__constant__ float c_mean[6];
__constant__ float c_std[6];

// acos via Abramowitz-Stegun 4.4.45 (4 coeff): abs err <= 6.7e-5 rad.
__device__ __forceinline__ float fast_acosf(float x) {
    float ax = fabsf(x);
    float t  = 1.0f - ax;
    float s  = t * rsqrtf(t);                 // sqrt(1-ax), MUFU.RSQ
    float p  = fmaf(ax, -0.0187293f, 0.0742610f);
    p = fmaf(ax, p, -0.2121144f);
    p = fmaf(ax, p,  1.5707288f);
    float a = s * p;
    return (x >= 0.0f) ? a : (3.14159265358979f - a);
}

// q (mean eig), p (spread), cp = cos(acos(r)/3); normalization folded via rs^3.
__device__ __forceinline__ void eig_qpc(
    float a00, float a01, float a02, float a11, float a12, float a22,
    float& q, float& p, float& cp)
{
    q = (a00 + a11 + a22) * (1.0f / 3.0f);
    float c00 = a00 - q, c11 = a11 - q, c22 = a22 - q;
    float p2 = c00*c00 + c11*c11 + c22*c22
             + 2.0f * (a01*a01 + a02*a02 + a12*a12);
    float p2s = p2 * (1.0f / 6.0f);
    float rs  = (p2s > 0.0f) ? rsqrtf(p2s) : 0.0f;   // MUFU.RSQ
    p = p2s * rs;                                     // = sqrt(p2/6)

    float detC = c00 * (c11*c22 - a12*a12)
               - a01 * (a01*c22 - a12*a02)
               + a02 * (a01*a12 - c11*a02);
    float rs3 = rs * rs * rs;
    float r = 0.5f * detC * rs3;
    r = fminf(fmaxf(r, -1.0f + 1e-7f), 1.0f - 1e-7f);
    float phi = fast_acosf(r) * (1.0f / 3.0f);
    cp = __cosf(phi);   // phi in [0, pi/3]
}

__device__ __forceinline__ float f4_get(const float4& v, int lane) {
    switch (lane) {
        case 0: return v.x;
        case 1: return v.y;
        case 2: return v.z;
        default: return v.w;
    }
}

__global__ void __launch_bounds__(BLOCK, 6)
ani_loss_kernel(const float*  __restrict__ input,
                const float*  __restrict__ target,
                const int*    __restrict__ mask,
                float*        __restrict__ out)
{
    int i = blockIdx.x * blockDim.x + threadIdx.x;   // one thread = 4 voxels
    int b = i / Q4;
    int s = i - b * Q4;

    const float4* in4 = (const float4*)input  + (size_t)b * 6 * Q4 + s;
    const float4* tg4 = (const float4*)target + (size_t)b * 6 * Q4 + s;
    const int4*   mk4 = (const int4*)mask     + (size_t)b * Q4 + s;

    // ---- phase 1: mask + input channels -> per-lane input anisotropy ----
    int4 mi = __ldcs(mk4);

    float4 x[6];
    #pragma unroll
    for (int c = 0; c < 6; c++)
        x[c] = __ldcs(&in4[c * Q4]);

    float iani[4];
    #pragma unroll
    for (int lane = 0; lane < 4; lane++) {
        float a[6];
        #pragma unroll
        for (int c = 0; c < 6; c++)
            a[c] = fmaf(f4_get(x[c], lane), c_std[c], c_mean[c]);
        float q, p, cp;
        eig_qpc(a[0], a[1], a[2], a[3], a[4], a[5], q, p, cp);
        iani[lane] = 3.0f * p * cp;          // l2 - 0.5*(l0+l1) = 3*p*cos(phi)
    }

    // ---- phase 2: target channels -> difference, masked accumulate ----
    #pragma unroll
    for (int c = 0; c < 6; c++)
        x[c] = __ldcs(&tg4[c * Q4]);

    int mlane[4] = {mi.x, mi.y, mi.z, mi.w};
    float lsum = 0.0f;
    int   lcnt = 0;

    #pragma unroll
    for (int lane = 0; lane < 4; lane++) {
        float a[6];
        #pragma unroll
        for (int c = 0; c < 6; c++)
            a[c] = fmaf(f4_get(x[c], lane), c_std[c], c_mean[c]);
        float q, p, cp;
        eig_qpc(a[0], a[1], a[2], a[3], a[4], a[5], q, p, cp);
        float tani = q - p * cp;             // 0.5*(l0+l1)
        float mf = (float)mlane[lane];
        lsum += fabsf(iani[lane] - tani) * mf;
        lcnt += mlane[lane];
    }

    // ---- reduction ----
    #pragma unroll
    for (int o = 16; o > 0; o >>= 1) {
        lsum += __shfl_down_sync(0xFFFFFFFFu, lsum, o);
        lcnt += __shfl_down_sync(0xFFFFFFFFu, lcnt, o);
    }

    __shared__ float ssum[8];
    __shared__ int   scnt[8];
    __shared__ bool  isLast;
    int wid = threadIdx.x >> 5;
    int lid = threadIdx.x & 31;
    if (lid == 0) { ssum[wid] = lsum; scnt[wid] = lcnt; }
    __syncthreads();

    if (wid == 0) {
        float bs = (lid < (BLOCK >> 5)) ? ssum[lid] : 0.0f;
        int   bc = (lid < (BLOCK >> 5)) ? scnt[lid] : 0;
        #pragma unroll
        for (int o = 4; o > 0; o >>= 1) {
            bs += __shfl_down_sync(0xFFFFFFFFu, bs, o);
            bc += __shfl_down_sync(0xFFFFFFFFu, bc, o);
        }
        if (lid == 0) {
            atomicAdd(&g_sum, (double)bs);
            atomicAdd(&g_cnt, bc);
            __threadfence();
            unsigned t = atomicAdd(&g_retire, 1u);
            isLast = (t == (unsigned)(gridDim.x - 1));
        }
    }
    __syncthreads();

    // Last block finalizes and resets accumulators (graph-replay safe).
    if (isLast && threadIdx.x == 0) {
        double s_tot = atomicAdd(&g_sum, 0.0);
        int    c_tot = atomicAdd(&g_cnt, 0);
        double n = (c_tot < 1) ? 1.0 : (double)c_tot;
        out[0] = (float)(s_tot / n);
        atomicExch((unsigned long long*)&g_sum, 0ull);
        atomicExch(&g_cnt, 0);
        __threadfence();
        atomicExch(&g_retire, 0u);
    }
}

extern "C" void kernel_launch(void* const* d_in, const int* in_sizes, int n_in,
                              void* d_out, int out_size)
{
    const float* input   = (const float*)d_in[0];
    const float* target  = (const float*)d_in[1];
    const int*   mask    = (const int*)d_in[2];
    const float* gt_mean = (const float*)d_in[3];
    const float* gt_std  = (const float*)d_in[4];
    float* out = (float*)d_out;

    // D2D memcpy nodes: graph-capturable, re-executed on every replay.
    cudaMemcpyToSymbolAsync(c_mean, gt_mean, 6 * sizeof(float), 0,
                            cudaMemcpyDeviceToDevice, 0);
    cudaMemcpyToSymbolAsync(c_std,  gt_std,  6 * sizeof(float), 0,
                            cudaMemcpyDeviceToDevice, 0);

    ani_loss_kernel<<<GRID, BLOCK>>>(input, target, mask, out);
}

// round 7
// speedup vs baseline: 1.0287x; 1.0287x over previous
#include <cuda_runtime.h>

#define HWD (96*96*96)        // 884736
#define NB  4
#define NVOX (NB*HWD)         // 3538944
#define Q4  (HWD/4)           // 221184 float4 groups per (b, channel)
#define BLOCK 256
#define GRID  (NVOX / 4 / BLOCK)   // 3456, exact

__device__ double       g_sum    = 0.0;
__device__ int          g_cnt    = 0;
__device__ unsigned int g_retire = 0u;

// Warp-uniform scale/shift in constant memory (LDCU -> uniform regs).
__constant__ float c_mean[6];
__constant__ float c_std[6];

// acos via Abramowitz-Stegun 4.4.45 (4 coeff): abs err <= 6.7e-5 rad.
__device__ __forceinline__ float fast_acosf(float x) {
    float ax = fabsf(x);
    float t  = 1.0f - ax;
    float s  = t * rsqrtf(t);                 // sqrt(1-ax), MUFU.RSQ
    float p  = fmaf(ax, -0.0187293f, 0.0742610f);
    p = fmaf(ax, p, -0.2121144f);
    p = fmaf(ax, p,  1.5707288f);
    float a = s * p;
    return (x >= 0.0f) ? a : (3.14159265358979f - a);
}

// q (mean eig), p (spread), cp = cos(acos(r)/3); normalization folded via rs^3.
__device__ __forceinline__ void eig_qpc(
    float a00, float a01, float a02, float a11, float a12, float a22,
    float& q, float& p, float& cp)
{
    q = (a00 + a11 + a22) * (1.0f / 3.0f);
    float c00 = a00 - q, c11 = a11 - q, c22 = a22 - q;
    float p2 = c00*c00 + c11*c11 + c22*c22
             + 2.0f * (a01*a01 + a02*a02 + a12*a12);
    float p2s = p2 * (1.0f / 6.0f);
    float rs  = (p2s > 0.0f) ? rsqrtf(p2s) : 0.0f;   // MUFU.RSQ
    p = p2s * rs;                                     // = sqrt(p2/6)

    float detC = c00 * (c11*c22 - a12*a12)
               - a01 * (a01*c22 - a12*a02)
               + a02 * (a01*a12 - c11*a02);
    float rs3 = rs * rs * rs;
    float r = 0.5f * detC * rs3;
    r = fminf(fmaxf(r, -1.0f + 1e-7f), 1.0f - 1e-7f);
    float phi = fast_acosf(r) * (1.0f / 3.0f);
    cp = __cosf(phi);   // phi in [0, pi/3]
}

__device__ __forceinline__ float f4_get(const float4& v, int lane) {
    switch (lane) {
        case 0: return v.x;
        case 1: return v.y;
        case 2: return v.z;
        default: return v.w;
    }
}

__global__ void __launch_bounds__(BLOCK, 5)
ani_loss_kernel(const float*  __restrict__ input,
                const float*  __restrict__ target,
                const int*    __restrict__ mask,
                float*        __restrict__ out)
{
    int i = blockIdx.x * blockDim.x + threadIdx.x;   // one thread = 4 voxels
    int b = i / Q4;
    int s = i - b * Q4;

    const float4* in4 = (const float4*)input  + (size_t)b * 6 * Q4 + s;
    const float4* tg4 = (const float4*)target + (size_t)b * 6 * Q4 + s;
    const int4*   mk4 = (const int4*)mask     + (size_t)b * Q4 + s;

    // ---- phase 1: mask + input channels -> per-lane input anisotropy ----
    int4 mi = __ldcs(mk4);

    float4 x[6];
    #pragma unroll
    for (int c = 0; c < 6; c++)
        x[c] = __ldcs(&in4[c * Q4]);

    float iani[4];
    #pragma unroll
    for (int lane = 0; lane < 4; lane++) {
        float a[6];
        #pragma unroll
        for (int c = 0; c < 6; c++)
            a[c] = fmaf(f4_get(x[c], lane), c_std[c], c_mean[c]);
        float q, p, cp;
        eig_qpc(a[0], a[1], a[2], a[3], a[4], a[5], q, p, cp);
        iani[lane] = 3.0f * p * cp;          // l2 - 0.5*(l0+l1) = 3*p*cos(phi)
    }

    // ---- phase 2: target channels -> difference, masked accumulate ----
    #pragma unroll
    for (int c = 0; c < 6; c++)
        x[c] = __ldcs(&tg4[c * Q4]);

    int mlane[4] = {mi.x, mi.y, mi.z, mi.w};
    float lsum = 0.0f;
    int   lcnt = 0;

    #pragma unroll
    for (int lane = 0; lane < 4; lane++) {
        float a[6];
        #pragma unroll
        for (int c = 0; c < 6; c++)
            a[c] = fmaf(f4_get(x[c], lane), c_std[c], c_mean[c]);
        float q, p, cp;
        eig_qpc(a[0], a[1], a[2], a[3], a[4], a[5], q, p, cp);
        float tani = q - p * cp;             // 0.5*(l0+l1)
        float mf = (float)mlane[lane];
        lsum += fabsf(iani[lane] - tani) * mf;
        lcnt += mlane[lane];
    }

    // ---- reduction ----
    #pragma unroll
    for (int o = 16; o > 0; o >>= 1) {
        lsum += __shfl_down_sync(0xFFFFFFFFu, lsum, o);
        lcnt += __shfl_down_sync(0xFFFFFFFFu, lcnt, o);
    }

    __shared__ float ssum[8];
    __shared__ int   scnt[8];
    __shared__ bool  isLast;
    int wid = threadIdx.x >> 5;
    int lid = threadIdx.x & 31;
    if (lid == 0) { ssum[wid] = lsum; scnt[wid] = lcnt; }
    __syncthreads();

    if (wid == 0) {
        float bs = (lid < (BLOCK >> 5)) ? ssum[lid] : 0.0f;
        int   bc = (lid < (BLOCK >> 5)) ? scnt[lid] : 0;
        #pragma unroll
        for (int o = 4; o > 0; o >>= 1) {
            bs += __shfl_down_sync(0xFFFFFFFFu, bs, o);
            bc += __shfl_down_sync(0xFFFFFFFFu, bc, o);
        }
        if (lid == 0) {
            atomicAdd(&g_sum, (double)bs);
            atomicAdd(&g_cnt, bc);
            __threadfence();
            unsigned t = atomicAdd(&g_retire, 1u);
            isLast = (t == (unsigned)(gridDim.x - 1));
        }
    }
    __syncthreads();

    // Last block finalizes and resets accumulators (graph-replay safe).
    if (isLast && threadIdx.x == 0) {
        double s_tot = atomicAdd(&g_sum, 0.0);
        int    c_tot = atomicAdd(&g_cnt, 0);
        double n = (c_tot < 1) ? 1.0 : (double)c_tot;
        out[0] = (float)(s_tot / n);
        atomicExch((unsigned long long*)&g_sum, 0ull);
        atomicExch(&g_cnt, 0);
        __threadfence();
        atomicExch(&g_retire, 0u);
    }
}

extern "C" void kernel_launch(void* const* d_in, const int* in_sizes, int n_in,
                              void* d_out, int out_size)
{
    const float* input   = (const float*)d_in[0];
    const float* target  = (const float*)d_in[1];
    const int*   mask    = (const int*)d_in[2];
    const float* gt_mean = (const float*)d_in[3];
    const float* gt_std  = (const float*)d_in[4];
    float* out = (float*)d_out;

    // D2D memcpy nodes: graph-capturable, re-executed on every replay.
    cudaMemcpyToSymbolAsync(c_mean, gt_mean, 6 * sizeof(float), 0,
                            cudaMemcpyDeviceToDevice, 0);
    cudaMemcpyToSymbolAsync(c_std,  gt_std,  6 * sizeof(float), 0,
                            cudaMemcpyDeviceToDevice, 0);

    ani_loss_kernel<<<GRID, BLOCK>>>(input, target, mask, out);
}

// round 9
// speedup vs baseline: 1.3250x; 1.2880x over previous
#include <cuda_runtime.h>

#define HWD (96*96*96)        // 884736
#define NB  4
#define NVOX (NB*HWD)         // 3538944
#define Q4  (HWD/4)           // 221184 float4 groups per (b, channel)
#define BLOCK 256
#define GRID  (NVOX / 4 / BLOCK)   // 3456, exact

__device__ double       g_sum    = 0.0;
__device__ int          g_cnt    = 0;
__device__ unsigned int g_retire = 0u;

__device__ __forceinline__ void cp_async16(void* smem_dst, const void* gsrc) {
    unsigned saddr = (unsigned)__cvta_generic_to_shared(smem_dst);
    asm volatile("cp.async.cg.shared.global [%0], [%1], 16;"
                 :: "r"(saddr), "l"(gsrc) : "memory");
}

// acos via Abramowitz-Stegun 4.4.45 (4 coeff): abs err <= 6.7e-5 rad.
__device__ __forceinline__ float fast_acosf(float x) {
    float ax = fabsf(x);
    float t  = 1.0f - ax;
    float s  = t * rsqrtf(t);                 // sqrt(1-ax), MUFU.RSQ
    float p  = fmaf(ax, -0.0187293f, 0.0742610f);
    p = fmaf(ax, p, -0.2121144f);
    p = fmaf(ax, p,  1.5707288f);
    float a = s * p;
    return (x >= 0.0f) ? a : (3.14159265358979f - a);
}

// q (mean eig), p (spread), cp = cos(acos(r)/3); normalization folded via rs^3.
__device__ __forceinline__ void eig_qpc(
    float a00, float a01, float a02, float a11, float a12, float a22,
    float& q, float& p, float& cp)
{
    q = (a00 + a11 + a22) * (1.0f / 3.0f);
    float c00 = a00 - q, c11 = a11 - q, c22 = a22 - q;
    float p2 = c00*c00 + c11*c11 + c22*c22
             + 2.0f * (a01*a01 + a02*a02 + a12*a12);
    float p2s = p2 * (1.0f / 6.0f);
    float rs  = (p2s > 0.0f) ? rsqrtf(p2s) : 0.0f;   // MUFU.RSQ
    p = p2s * rs;                                     // = sqrt(p2/6)

    float detC = c00 * (c11*c22 - a12*a12)
               - a01 * (a01*c22 - a12*a02)
               + a02 * (a01*a12 - c11*a02);
    float rs3 = rs * rs * rs;
    float r = 0.5f * detC * rs3;
    r = fminf(fmaxf(r, -1.0f + 1e-7f), 1.0f - 1e-7f);
    float phi = fast_acosf(r) * (1.0f / 3.0f);
    cp = __cosf(phi);   // phi in [0, pi/3]
}

__device__ __forceinline__ float f4_get(const float4& v, int lane) {
    switch (lane) {
        case 0: return v.x;
        case 1: return v.y;
        case 2: return v.z;
        default: return v.w;
    }
}

__global__ void __launch_bounds__(BLOCK, 5)
ani_loss_kernel(const float*  __restrict__ input,
                const float*  __restrict__ target,
                const int*    __restrict__ mask,
                const float*  __restrict__ gt_mean,
                const float*  __restrict__ gt_std,
                float*        __restrict__ out)
{
    __shared__ float4 stg[6 * BLOCK];   // target channels staged via cp.async

    int i = blockIdx.x * blockDim.x + threadIdx.x;   // one thread = 4 voxels
    int b = i / Q4;
    int s = i - b * Q4;

    const float4* in4 = (const float4*)input  + (size_t)b * 6 * Q4 + s;
    const float4* tg4 = (const float4*)target + (size_t)b * 6 * Q4 + s;
    const int4*   mk4 = (const int4*)mask     + (size_t)b * Q4 + s;

    float mean[6], stdv[6];
    #pragma unroll
    for (int c = 0; c < 6; c++) {
        mean[c] = __ldg(&gt_mean[c]);
        stdv[c] = __ldg(&gt_std[c]);
    }

    // ---- phase 1 loads: mask + input channels (registers) ----
    int4 mi = __ldcs(mk4);

    float4 x[6];
    #pragma unroll
    for (int c = 0; c < 6; c++)
        x[c] = __ldcs(&in4[c * Q4]);

    // ---- prefetch target channels into smem (no register cost in flight) ----
    #pragma unroll
    for (int c = 0; c < 6; c++)
        cp_async16(&stg[c * BLOCK + threadIdx.x], &tg4[c * Q4]);
    asm volatile("cp.async.commit_group;" ::: "memory");

    // ---- phase 1 compute: input anisotropy per lane ----
    float iani[4];
    #pragma unroll
    for (int lane = 0; lane < 4; lane++) {
        float a[6];
        #pragma unroll
        for (int c = 0; c < 6; c++)
            a[c] = fmaf(f4_get(x[c], lane), stdv[c], mean[c]);
        float q, p, cp;
        eig_qpc(a[0], a[1], a[2], a[3], a[4], a[5], q, p, cp);
        iani[lane] = 3.0f * p * cp;          // l2 - 0.5*(l0+l1) = 3*p*cos(phi)
    }

    // ---- phase 2: consume staged target data ----
    asm volatile("cp.async.wait_group 0;" ::: "memory");
    #pragma unroll
    for (int c = 0; c < 6; c++)
        x[c] = stg[c * BLOCK + threadIdx.x];

    int mlane[4] = {mi.x, mi.y, mi.z, mi.w};
    float lsum = 0.0f;
    int   lcnt = 0;

    #pragma unroll
    for (int lane = 0; lane < 4; lane++) {
        float a[6];
        #pragma unroll
        for (int c = 0; c < 6; c++)
            a[c] = fmaf(f4_get(x[c], lane), stdv[c], mean[c]);
        float q, p, cp;
        eig_qpc(a[0], a[1], a[2], a[3], a[4], a[5], q, p, cp);
        float tani = q - p * cp;             // 0.5*(l0+l1)
        float mf = (float)mlane[lane];
        lsum += fabsf(iani[lane] - tani) * mf;
        lcnt += mlane[lane];
    }

    // ---- reduction ----
    #pragma unroll
    for (int o = 16; o > 0; o >>= 1) {
        lsum += __shfl_down_sync(0xFFFFFFFFu, lsum, o);
        lcnt += __shfl_down_sync(0xFFFFFFFFu, lcnt, o);
    }

    __shared__ float ssum[8];
    __shared__ int   scnt[8];
    __shared__ bool  isLast;
    int wid = threadIdx.x >> 5;
    int lid = threadIdx.x & 31;
    if (lid == 0) { ssum[wid] = lsum; scnt[wid] = lcnt; }
    __syncthreads();

    if (wid == 0) {
        float bs = (lid < (BLOCK >> 5)) ? ssum[lid] : 0.0f;
        int   bc = (lid < (BLOCK >> 5)) ? scnt[lid] : 0;
        #pragma unroll
        for (int o = 4; o > 0; o >>= 1) {
            bs += __shfl_down_sync(0xFFFFFFFFu, bs, o);
            bc += __shfl_down_sync(0xFFFFFFFFu, bc, o);
        }
        if (lid == 0) {
            atomicAdd(&g_sum, (double)bs);
            atomicAdd(&g_cnt, bc);
            __threadfence();
            unsigned t = atomicAdd(&g_retire, 1u);
            isLast = (t == (unsigned)(gridDim.x - 1));
        }
    }
    __syncthreads();

    // Last block finalizes and resets accumulators (graph-replay safe).
    if (isLast && threadIdx.x == 0) {
        double s_tot = atomicAdd(&g_sum, 0.0);
        int    c_tot = atomicAdd(&g_cnt, 0);
        double n = (c_tot < 1) ? 1.0 : (double)c_tot;
        out[0] = (float)(s_tot / n);
        atomicExch((unsigned long long*)&g_sum, 0ull);
        atomicExch(&g_cnt, 0);
        __threadfence();
        atomicExch(&g_retire, 0u);
    }
}

extern "C" void kernel_launch(void* const* d_in, const int* in_sizes, int n_in,
                              void* d_out, int out_size)
{
    const float* input   = (const float*)d_in[0];
    const float* target  = (const float*)d_in[1];
    const int*   mask    = (const int*)d_in[2];
    const float* gt_mean = (const float*)d_in[3];
    const float* gt_std  = (const float*)d_in[4];
    float* out = (float*)d_out;

    ani_loss_kernel<<<GRID, BLOCK>>>(input, target, mask, gt_mean, gt_std, out);
}